// round 3
// baseline (speedup 1.0000x reference)
#include <cuda_runtime.h>
#include <math.h>

#define BB   128
#define TT   256
#define EE   384
#define HH   6
#define DHH  64
#define LL   6
#define VV   65
#define FFD  1536
#define BT   (BB*TT)          // 32768
#define E3   (3*EE)           // 1152
#define EPSV 1e-5f

// ---------------- scratch (device globals; no allocation allowed) ----------------
__device__ float g_x[BT*EE];        // residual stream
__device__ float g_h[BT*EE];        // LN output
__device__ float g_qkv[BT*E3];      // fused qkv
__device__ float g_att[BT*EE];      // attention output (concat heads)
__device__ float g_ff[BT*FFD];      // FF hidden
__device__ float g_wqkv[EE*E3];     // per-layer transposed qkv weights [E, 3E]
__device__ float g_nll[BT];         // per-token nll

// ---------------- embedding ----------------
__global__ void embed_kernel(const int* __restrict__ idx,
                             const float* __restrict__ tok,
                             const float* __restrict__ pos) {
    int i = blockIdx.x * blockDim.x + threadIdx.x;
    if (i >= BT * EE) return;
    int e  = i % EE;
    int bt = i / EE;
    int t  = bt % TT;
    g_x[i] = tok[idx[bt] * EE + e] + pos[t * EE + e];
}

// ---------------- layernorm: g_x -> g_h ----------------
__global__ void ln_kernel(const float* __restrict__ s, const float* __restrict__ b) {
    int tok = blockIdx.x;
    int tid = threadIdx.x;                 // 128 threads
    const float* row = g_x + (size_t)tok * EE;
    float v0 = row[tid], v1 = row[tid + 128], v2 = row[tid + 256];

    float sum = v0 + v1 + v2;
    __shared__ float red[4], red2[4];
    #pragma unroll
    for (int o = 16; o; o >>= 1) sum += __shfl_xor_sync(~0u, sum, o);
    if ((tid & 31) == 0) red[tid >> 5] = sum;
    __syncthreads();
    float mean = (red[0] + red[1] + red[2] + red[3]) * (1.f / EE);

    float d0 = v0 - mean, d1 = v1 - mean, d2 = v2 - mean;
    float vs = d0 * d0 + d1 * d1 + d2 * d2;
    #pragma unroll
    for (int o = 16; o; o >>= 1) vs += __shfl_xor_sync(~0u, vs, o);
    if ((tid & 31) == 0) red2[tid >> 5] = vs;
    __syncthreads();
    float var = (red2[0] + red2[1] + red2[2] + red2[3]) * (1.f / EE);
    float inv = rsqrtf(var + EPSV);

    float* out = g_h + (size_t)tok * EE;
    out[tid]       = d0 * inv * s[tid]       + b[tid];
    out[tid + 128] = d1 * inv * s[tid + 128] + b[tid + 128];
    out[tid + 256] = d2 * inv * s[tid + 256] + b[tid + 256];
}

// ---------------- qkv weight transpose for layer l: [H,E,DH]x3 -> [E, 3E] ----------------
__global__ void tq_kernel(const float* __restrict__ Wq, const float* __restrict__ Wk,
                          const float* __restrict__ Wv, int l) {
    int i = blockIdx.x * blockDim.x + threadIdx.x;
    if (i >= HH * EE * DHH) return;
    int d = i % DHH;
    int e = (i / DHH) % EE;
    int h = i / (DHH * EE);
    int src = ((l * HH + h) * EE + e) * DHH + d;
    int col = h * DHH + d;
    g_wqkv[e * E3 + col]          = Wq[src];
    g_wqkv[e * E3 + EE + col]     = Wk[src];
    g_wqkv[e * E3 + 2 * EE + col] = Wv[src];
}

// ---------------- 128x128x8 SGEMM, fused epilogue ----------------
// MODE bits: 1 = +bias[n], 2 = +resid[m*N+n], 4 = relu
template <int MODE>
__global__ void gemm128(const float* __restrict__ A, const float* __restrict__ B,
                        const float* __restrict__ bias, const float* __restrict__ resid,
                        float* __restrict__ C, int M, int N, int K) {
    __shared__ float As[8][128];
    __shared__ float Bs[8][128];
    int m0 = blockIdx.x * 128;    // M tile (fast dim -> consecutive blocks share B tile)
    int n0 = blockIdx.y * 128;
    int tid = threadIdx.x;        // 256
    int row_c = (tid >> 4) << 3;  // 0..120
    int col_c = (tid & 15) << 3;  // 0..120

    float acc[8][8];
    #pragma unroll
    for (int i = 0; i < 8; i++)
        #pragma unroll
        for (int j = 0; j < 8; j++) acc[i][j] = 0.f;

    int ar = tid >> 1;            // 0..127
    int ac = (tid & 1) << 2;      // 0 / 4
    int br = tid >> 5;            // 0..7
    int bc = (tid & 31) << 2;     // 0..124

    for (int k0 = 0; k0 < K; k0 += 8) {
        float4 av = *(const float4*)(A + (size_t)(m0 + ar) * K + k0 + ac);
        float4 bv = *(const float4*)(B + (size_t)(k0 + br) * N + n0 + bc);
        As[ac + 0][ar] = av.x; As[ac + 1][ar] = av.y;
        As[ac + 2][ar] = av.z; As[ac + 3][ar] = av.w;
        *(float4*)&Bs[br][bc] = bv;
        __syncthreads();
        #pragma unroll
        for (int k = 0; k < 8; k++) {
            float a[8], bb[8];
            #pragma unroll
            for (int i = 0; i < 8; i++) a[i] = As[k][row_c + i];
            #pragma unroll
            for (int j = 0; j < 8; j++) bb[j] = Bs[k][col_c + j];
            #pragma unroll
            for (int i = 0; i < 8; i++)
                #pragma unroll
                for (int j = 0; j < 8; j++)
                    acc[i][j] = fmaf(a[i], bb[j], acc[i][j]);
        }
        __syncthreads();
    }

    #pragma unroll
    for (int i = 0; i < 8; i++) {
        int m = m0 + row_c + i;
        #pragma unroll
        for (int j = 0; j < 8; j++) {
            int n = n0 + col_c + j;
            float v = acc[i][j];
            if (MODE & 1) v += bias[n];
            if (MODE & 2) v += resid[(size_t)m * N + n];
            if (MODE & 4) v = fmaxf(v, 0.f);
            C[(size_t)m * N + n] = v;
        }
    }
}

// ---------------- attention: one block per (b,h), flash-style online softmax ----------------
__global__ void attn_kernel() {
    extern __shared__ float sm[];
    float* Ks = sm;                 // [256][64]
    float* Vs = sm + TT * DHH;      // [256][64]
    int b = blockIdx.x / HH;
    int h = blockIdx.x % HH;
    int tid = threadIdx.x;          // 256

    const float* base = g_qkv + (size_t)b * TT * E3;
    for (int i = tid; i < TT * DHH / 4; i += blockDim.x) {
        int srow = i >> 4;          // 16 float4 per row
        int c4 = (i & 15) << 2;
        *(float4*)&Ks[srow * DHH + c4] = *(const float4*)(base + (size_t)srow * E3 + EE + h * DHH + c4);
        *(float4*)&Vs[srow * DHH + c4] = *(const float4*)(base + (size_t)srow * E3 + 2 * EE + h * DHH + c4);
    }
    __syncthreads();

    int t = tid;
    float q[DHH];
    const float* qp = base + (size_t)t * E3 + h * DHH;
    #pragma unroll
    for (int d = 0; d < DHH; d++) q[d] = qp[d] * 0.125f;   // scale = DH^-0.5

    float acc[DHH];
    #pragma unroll
    for (int d = 0; d < DHH; d++) acc[d] = 0.f;
    float m = -1e30f, l = 0.f;

    for (int s = 0; s < TT; s++) {
        if (s > t) break;
        float sc = 0.f;
        #pragma unroll
        for (int d = 0; d < DHH; d++) sc = fmaf(q[d], Ks[s * DHH + d], sc);
        float nm = fmaxf(m, sc);
        float corr = __expf(m - nm);
        float p = __expf(sc - nm);
        l = l * corr + p;
        #pragma unroll
        for (int d = 0; d < DHH; d++)
            acc[d] = fmaf(acc[d], corr, p * Vs[s * DHH + d]);
        m = nm;
    }

    float inv = 1.f / l;
    float* op = g_att + ((size_t)(b * TT + t)) * EE + h * DHH;
    #pragma unroll
    for (int d = 0; d < DHH; d++) op[d] = acc[d] * inv;
}

// ---------------- fused logits + log_softmax + nll (reads g_h) ----------------
__global__ void logits_kernel(const float* __restrict__ Wout, const float* __restrict__ bout,
                              const int* __restrict__ tgt, float* __restrict__ out) {
    __shared__ float hs[EE];
    __shared__ float sl[128];
    __shared__ float slog[VV];
    int tok = blockIdx.x;
    int tid = threadIdx.x;          // 128
    const float* row = g_h + (size_t)tok * EE;
    hs[tid] = row[tid]; hs[tid + 128] = row[tid + 128]; hs[tid + 256] = row[tid + 256];
    __syncthreads();

    float logit = -1e30f;
    if (tid < VV) {
        float s = bout[tid];
        #pragma unroll 4
        for (int e = 0; e < EE; e++) s = fmaf(hs[e], Wout[e * VV + tid], s);
        logit = s;
        slog[tid] = s;
        out[(size_t)tok * VV + tid] = s;
    }
    sl[tid] = logit;
    __syncthreads();
    for (int o = 64; o; o >>= 1) { if (tid < o) sl[tid] = fmaxf(sl[tid], sl[tid + o]); __syncthreads(); }
    float mx = sl[0];
    __syncthreads();
    sl[tid] = (tid < VV) ? __expf(logit - mx) : 0.f;
    __syncthreads();
    for (int o = 64; o; o >>= 1) { if (tid < o) sl[tid] += sl[tid + o]; __syncthreads(); }
    if (tid == 0) {
        float logZ = mx + __logf(sl[0]);
        g_nll[tok] = logZ - slog[tgt[tok]];
    }
}

// ---------------- deterministic loss reduction ----------------
__global__ void loss_kernel(float* __restrict__ out) {
    __shared__ float red[256];
    float s = 0.f;
    for (int i = threadIdx.x; i < BT; i += 256) s += g_nll[i];
    red[threadIdx.x] = s;
    __syncthreads();
    for (int o = 128; o; o >>= 1) { if (threadIdx.x < o) red[threadIdx.x] += red[threadIdx.x + o]; __syncthreads(); }
    if (threadIdx.x == 0) out[(size_t)BT * VV] = red[0] * (1.f / BT);
}

// ---------------- host orchestration ----------------
extern "C" void kernel_launch(void* const* d_in, const int* in_sizes, int n_in,
                              void* d_out, int out_size) {
    const int*   idx  = (const int*)d_in[0];
    const int*   tgt  = (const int*)d_in[1];
    const float* tok  = (const float*)d_in[2];
    const float* pos  = (const float*)d_in[3];
    const float* Wq   = (const float*)d_in[4];
    const float* Wk   = (const float*)d_in[5];
    const float* Wv   = (const float*)d_in[6];
    const float* Wo   = (const float*)d_in[7];
    const float* bo   = (const float*)d_in[8];
    const float* l1s  = (const float*)d_in[9];
    const float* l1b  = (const float*)d_in[10];
    const float* l2s  = (const float*)d_in[11];
    const float* l2b  = (const float*)d_in[12];
    const float* W1   = (const float*)d_in[13];
    const float* b1   = (const float*)d_in[14];
    const float* W2   = (const float*)d_in[15];
    const float* b2   = (const float*)d_in[16];
    const float* lnfs = (const float*)d_in[17];
    const float* lnfb = (const float*)d_in[18];
    const float* Wout = (const float*)d_in[19];
    const float* bout = (const float*)d_in[20];
    float* out = (float*)d_out;

    cudaFuncSetAttribute(attn_kernel, cudaFuncAttributeMaxDynamicSharedMemorySize,
                         2 * TT * DHH * (int)sizeof(float));

    float *px, *ph, *pqkv, *patt, *pff, *pwqkv;
    cudaGetSymbolAddress((void**)&px,    g_x);
    cudaGetSymbolAddress((void**)&ph,    g_h);
    cudaGetSymbolAddress((void**)&pqkv,  g_qkv);
    cudaGetSymbolAddress((void**)&patt,  g_att);
    cudaGetSymbolAddress((void**)&pff,   g_ff);
    cudaGetSymbolAddress((void**)&pwqkv, g_wqkv);

    embed_kernel<<<(BT * EE + 255) / 256, 256>>>(idx, tok, pos);

    for (int l = 0; l < LL; l++) {
        ln_kernel<<<BT, 128>>>(l1s + l * EE, l1b + l * EE);
        tq_kernel<<<(HH * EE * DHH + 255) / 256, 256>>>(Wq, Wk, Wv, l);
        // qkv = h @ Wqkv_t  [BT,384]@[384,1152]
        gemm128<0><<<dim3(BT / 128, E3 / 128), 256>>>(ph, pwqkv, nullptr, nullptr, pqkv, BT, E3, EE);
        attn_kernel<<<BB * HH, TT, 2 * TT * DHH * sizeof(float)>>>();
        // x = x + att @ Wo + bo
        gemm128<1 | 2><<<dim3(BT / 128, EE / 128), 256>>>(patt, Wo + (size_t)l * EE * EE, bo + l * EE, px, px, BT, EE, EE);
        ln_kernel<<<BT, 128>>>(l2s + l * EE, l2b + l * EE);
        // ff = relu(h @ W1 + b1)
        gemm128<1 | 4><<<dim3(BT / 128, FFD / 128), 256>>>(ph, W1 + (size_t)l * EE * FFD, b1 + l * FFD, nullptr, pff, BT, FFD, EE);
        // x = x + ff @ W2 + b2
        gemm128<1 | 2><<<dim3(BT / 128, EE / 128), 256>>>(pff, W2 + (size_t)l * FFD * EE, b2 + l * EE, px, px, BT, EE, FFD);
    }

    ln_kernel<<<BT, 128>>>(lnfs, lnfb);
    logits_kernel<<<BT, 128>>>(Wout, bout, tgt, out);
    loss_kernel<<<1, 256>>>(out);
}

// round 4
// speedup vs baseline: 1.0002x; 1.0002x over previous
#include <cuda_runtime.h>
#include <math.h>

#define BB   128
#define TT   256
#define EE   384
#define HH   6
#define DHH  64
#define LL   6
#define VV   65
#define FFD  1536
#define BT   (BB*TT)          // 32768
#define E3   (3*EE)           // 1152
#define EPSV 1e-5f

// ---------------- scratch (device globals; no allocation allowed) ----------------
__device__ float g_x[BT*EE];        // residual stream
__device__ float g_h[BT*EE];        // LN output
__device__ float g_qkv[BT*E3];      // fused qkv
__device__ float g_att[BT*EE];      // attention output (concat heads)
__device__ float g_ff[BT*FFD];      // FF hidden
__device__ float g_wqkv[EE*E3];     // per-layer transposed qkv weights [E, 3E]
__device__ float g_nll[BT];         // per-token nll

// ---------------- embedding ----------------
__global__ void embed_kernel(const int* __restrict__ idx,
                             const float* __restrict__ tok,
                             const float* __restrict__ pos) {
    int i = blockIdx.x * blockDim.x + threadIdx.x;
    if (i >= BT * EE) return;
    int e  = i % EE;
    int bt = i / EE;
    int t  = bt % TT;
    g_x[i] = tok[idx[bt] * EE + e] + pos[t * EE + e];
}

// ---------------- layernorm: g_x -> g_h ----------------
__global__ void ln_kernel(const float* __restrict__ s, const float* __restrict__ b) {
    int tok = blockIdx.x;
    int tid = threadIdx.x;                 // 128 threads
    const float* row = g_x + (size_t)tok * EE;
    float v0 = row[tid], v1 = row[tid + 128], v2 = row[tid + 256];

    float sum = v0 + v1 + v2;
    __shared__ float red[4], red2[4];
    #pragma unroll
    for (int o = 16; o; o >>= 1) sum += __shfl_xor_sync(~0u, sum, o);
    if ((tid & 31) == 0) red[tid >> 5] = sum;
    __syncthreads();
    float mean = (red[0] + red[1] + red[2] + red[3]) * (1.f / EE);

    float d0 = v0 - mean, d1 = v1 - mean, d2 = v2 - mean;
    float vs = d0 * d0 + d1 * d1 + d2 * d2;
    #pragma unroll
    for (int o = 16; o; o >>= 1) vs += __shfl_xor_sync(~0u, vs, o);
    if ((tid & 31) == 0) red2[tid >> 5] = vs;
    __syncthreads();
    float var = (red2[0] + red2[1] + red2[2] + red2[3]) * (1.f / EE);
    float inv = rsqrtf(var + EPSV);

    float* out = g_h + (size_t)tok * EE;
    out[tid]       = d0 * inv * s[tid]       + b[tid];
    out[tid + 128] = d1 * inv * s[tid + 128] + b[tid + 128];
    out[tid + 256] = d2 * inv * s[tid + 256] + b[tid + 256];
}

// ---------------- qkv weight transpose for layer l: [H,E,DH]x3 -> [E, 3E] ----------------
__global__ void tq_kernel(const float* __restrict__ Wq, const float* __restrict__ Wk,
                          const float* __restrict__ Wv, int l) {
    int i = blockIdx.x * blockDim.x + threadIdx.x;
    if (i >= HH * EE * DHH) return;
    int d = i % DHH;
    int e = (i / DHH) % EE;
    int h = i / (DHH * EE);
    int src = ((l * HH + h) * EE + e) * DHH + d;
    int col = h * DHH + d;
    g_wqkv[e * E3 + col]          = Wq[src];
    g_wqkv[e * E3 + EE + col]     = Wk[src];
    g_wqkv[e * E3 + 2 * EE + col] = Wv[src];
}

// ---------------- 128x128x8 SGEMM, fused epilogue ----------------
// MODE bits: 1 = +bias[n], 2 = +resid[m*N+n], 4 = relu
template <int MODE>
__global__ void gemm128(const float* __restrict__ A, const float* __restrict__ B,
                        const float* __restrict__ bias, const float* __restrict__ resid,
                        float* __restrict__ C, int M, int N, int K) {
    __shared__ float As[8][128];
    __shared__ float Bs[8][128];
    int m0 = blockIdx.x * 128;    // M tile (fast dim -> consecutive blocks share B tile)
    int n0 = blockIdx.y * 128;
    int tid = threadIdx.x;        // 256
    int row_c = (tid >> 4) << 3;  // 0..120
    int col_c = (tid & 15) << 3;  // 0..120

    float acc[8][8];
    #pragma unroll
    for (int i = 0; i < 8; i++)
        #pragma unroll
        for (int j = 0; j < 8; j++) acc[i][j] = 0.f;

    int ar = tid >> 1;            // 0..127
    int ac = (tid & 1) << 2;      // 0 / 4
    int br = tid >> 5;            // 0..7
    int bc = (tid & 31) << 2;     // 0..124

    for (int k0 = 0; k0 < K; k0 += 8) {
        float4 av = *(const float4*)(A + (size_t)(m0 + ar) * K + k0 + ac);
        float4 bv = *(const float4*)(B + (size_t)(k0 + br) * N + n0 + bc);
        As[ac + 0][ar] = av.x; As[ac + 1][ar] = av.y;
        As[ac + 2][ar] = av.z; As[ac + 3][ar] = av.w;
        *(float4*)&Bs[br][bc] = bv;
        __syncthreads();
        #pragma unroll
        for (int k = 0; k < 8; k++) {
            float a[8], bb[8];
            #pragma unroll
            for (int i = 0; i < 8; i++) a[i] = As[k][row_c + i];
            #pragma unroll
            for (int j = 0; j < 8; j++) bb[j] = Bs[k][col_c + j];
            #pragma unroll
            for (int i = 0; i < 8; i++)
                #pragma unroll
                for (int j = 0; j < 8; j++)
                    acc[i][j] = fmaf(a[i], bb[j], acc[i][j]);
        }
        __syncthreads();
    }

    #pragma unroll
    for (int i = 0; i < 8; i++) {
        int m = m0 + row_c + i;
        #pragma unroll
        for (int j = 0; j < 8; j++) {
            int n = n0 + col_c + j;
            float v = acc[i][j];
            if (MODE & 1) v += bias[n];
            if (MODE & 2) v += resid[(size_t)m * N + n];
            if (MODE & 4) v = fmaxf(v, 0.f);
            C[(size_t)m * N + n] = v;
        }
    }
}

// ---------------- attention: one block per (b,h), flash-style online softmax ----------------
__global__ void attn_kernel() {
    extern __shared__ float sm[];
    float* Ks = sm;                 // [256][64]
    float* Vs = sm + TT * DHH;      // [256][64]
    int b = blockIdx.x / HH;
    int h = blockIdx.x % HH;
    int tid = threadIdx.x;          // 256

    const float* base = g_qkv + (size_t)b * TT * E3;
    for (int i = tid; i < TT * DHH / 4; i += blockDim.x) {
        int srow = i >> 4;          // 16 float4 per row
        int c4 = (i & 15) << 2;
        *(float4*)&Ks[srow * DHH + c4] = *(const float4*)(base + (size_t)srow * E3 + EE + h * DHH + c4);
        *(float4*)&Vs[srow * DHH + c4] = *(const float4*)(base + (size_t)srow * E3 + 2 * EE + h * DHH + c4);
    }
    __syncthreads();

    int t = tid;
    float q[DHH];
    const float* qp = base + (size_t)t * E3 + h * DHH;
    #pragma unroll
    for (int d = 0; d < DHH; d++) q[d] = qp[d] * 0.125f;   // scale = DH^-0.5

    float acc[DHH];
    #pragma unroll
    for (int d = 0; d < DHH; d++) acc[d] = 0.f;
    float m = -1e30f, l = 0.f;

    for (int s = 0; s < TT; s++) {
        if (s > t) break;
        float sc = 0.f;
        #pragma unroll
        for (int d = 0; d < DHH; d++) sc = fmaf(q[d], Ks[s * DHH + d], sc);
        float nm = fmaxf(m, sc);
        float corr = __expf(m - nm);
        float p = __expf(sc - nm);
        l = l * corr + p;
        #pragma unroll
        for (int d = 0; d < DHH; d++)
            acc[d] = fmaf(acc[d], corr, p * Vs[s * DHH + d]);
        m = nm;
    }

    float inv = 1.f / l;
    float* op = g_att + ((size_t)(b * TT + t)) * EE + h * DHH;
    #pragma unroll
    for (int d = 0; d < DHH; d++) op[d] = acc[d] * inv;
}

// ---------------- fused logits + log_softmax + nll (reads g_h) ----------------
__global__ void logits_kernel(const float* __restrict__ Wout, const float* __restrict__ bout,
                              const int* __restrict__ tgt, float* __restrict__ out) {
    __shared__ float hs[EE];
    __shared__ float sl[128];
    __shared__ float slog[VV];
    int tok = blockIdx.x;
    int tid = threadIdx.x;          // 128
    const float* row = g_h + (size_t)tok * EE;
    hs[tid] = row[tid]; hs[tid + 128] = row[tid + 128]; hs[tid + 256] = row[tid + 256];
    __syncthreads();

    float logit = -1e30f;
    if (tid < VV) {
        float s = bout[tid];
        #pragma unroll 4
        for (int e = 0; e < EE; e++) s = fmaf(hs[e], Wout[e * VV + tid], s);
        logit = s;
        slog[tid] = s;
        out[(size_t)tok * VV + tid] = s;
    }
    sl[tid] = logit;
    __syncthreads();
    for (int o = 64; o; o >>= 1) { if (tid < o) sl[tid] = fmaxf(sl[tid], sl[tid + o]); __syncthreads(); }
    float mx = sl[0];
    __syncthreads();
    sl[tid] = (tid < VV) ? __expf(logit - mx) : 0.f;
    __syncthreads();
    for (int o = 64; o; o >>= 1) { if (tid < o) sl[tid] += sl[tid + o]; __syncthreads(); }
    if (tid == 0) {
        float logZ = mx + __logf(sl[0]);
        g_nll[tok] = logZ - slog[tgt[tok]];
    }
}

// ---------------- deterministic loss reduction ----------------
__global__ void loss_kernel(float* __restrict__ out) {
    __shared__ float red[256];
    float s = 0.f;
    for (int i = threadIdx.x; i < BT; i += 256) s += g_nll[i];
    red[threadIdx.x] = s;
    __syncthreads();
    for (int o = 128; o; o >>= 1) { if (threadIdx.x < o) red[threadIdx.x] += red[threadIdx.x + o]; __syncthreads(); }
    if (threadIdx.x == 0) out[(size_t)BT * VV] = red[0] * (1.f / BT);
}

// ---------------- host orchestration ----------------
extern "C" void kernel_launch(void* const* d_in, const int* in_sizes, int n_in,
                              void* d_out, int out_size) {
    const int*   idx  = (const int*)d_in[0];
    const int*   tgt  = (const int*)d_in[1];
    const float* tok  = (const float*)d_in[2];
    const float* pos  = (const float*)d_in[3];
    const float* Wq   = (const float*)d_in[4];
    const float* Wk   = (const float*)d_in[5];
    const float* Wv   = (const float*)d_in[6];
    const float* Wo   = (const float*)d_in[7];
    const float* bo   = (const float*)d_in[8];
    const float* l1s  = (const float*)d_in[9];
    const float* l1b  = (const float*)d_in[10];
    const float* l2s  = (const float*)d_in[11];
    const float* l2b  = (const float*)d_in[12];
    const float* W1   = (const float*)d_in[13];
    const float* b1   = (const float*)d_in[14];
    const float* W2   = (const float*)d_in[15];
    const float* b2   = (const float*)d_in[16];
    const float* lnfs = (const float*)d_in[17];
    const float* lnfb = (const float*)d_in[18];
    const float* Wout = (const float*)d_in[19];
    const float* bout = (const float*)d_in[20];
    float* out = (float*)d_out;

    cudaFuncSetAttribute(attn_kernel, cudaFuncAttributeMaxDynamicSharedMemorySize,
                         2 * TT * DHH * (int)sizeof(float));

    float *px, *ph, *pqkv, *patt, *pff, *pwqkv;
    cudaGetSymbolAddress((void**)&px,    g_x);
    cudaGetSymbolAddress((void**)&ph,    g_h);
    cudaGetSymbolAddress((void**)&pqkv,  g_qkv);
    cudaGetSymbolAddress((void**)&patt,  g_att);
    cudaGetSymbolAddress((void**)&pff,   g_ff);
    cudaGetSymbolAddress((void**)&pwqkv, g_wqkv);

    embed_kernel<<<(BT * EE + 255) / 256, 256>>>(idx, tok, pos);

    for (int l = 0; l < LL; l++) {
        ln_kernel<<<BT, 128>>>(l1s + l * EE, l1b + l * EE);
        tq_kernel<<<(HH * EE * DHH + 255) / 256, 256>>>(Wq, Wk, Wv, l);
        // qkv = h @ Wqkv_t  [BT,384]@[384,1152]
        gemm128<0><<<dim3(BT / 128, E3 / 128), 256>>>(ph, pwqkv, nullptr, nullptr, pqkv, BT, E3, EE);
        attn_kernel<<<BB * HH, TT, 2 * TT * DHH * sizeof(float)>>>();
        // x = x + att @ Wo + bo
        gemm128<1 | 2><<<dim3(BT / 128, EE / 128), 256>>>(patt, Wo + (size_t)l * EE * EE, bo + l * EE, px, px, BT, EE, EE);
        ln_kernel<<<BT, 128>>>(l2s + l * EE, l2b + l * EE);
        // ff = relu(h @ W1 + b1)
        gemm128<1 | 4><<<dim3(BT / 128, FFD / 128), 256>>>(ph, W1 + (size_t)l * EE * FFD, b1 + l * FFD, nullptr, pff, BT, FFD, EE);
        // x = x + ff @ W2 + b2
        gemm128<1 | 2><<<dim3(BT / 128, EE / 128), 256>>>(pff, W2 + (size_t)l * FFD * EE, b2 + l * EE, px, px, BT, EE, FFD);
    }

    ln_kernel<<<BT, 128>>>(lnfs, lnfb);
    logits_kernel<<<BT, 128>>>(Wout, bout, tgt, out);
    loss_kernel<<<1, 256>>>(out);
}

// round 6
// speedup vs baseline: 2.4484x; 2.4478x over previous
#include <cuda_runtime.h>
#include <cstdint>
#include <math.h>

#define BB   128
#define TT   256
#define EE   384
#define HH   6
#define DHH  64
#define LL   6
#define VV   65
#define FFD  1536
#define BT   (BB*TT)          // 32768
#define E3   (3*EE)           // 1152
#define EPSV 1e-5f

// ======================= helpers =======================
__device__ __forceinline__ uint32_t smem_to_u32(const void* p) {
    uint32_t a;
    asm("{ .reg .u64 t; cvta.to.shared.u64 t, %1; cvt.u32.u64 %0, t; }" : "=r"(a) : "l"(p));
    return a;
}
__device__ __forceinline__ void cp_async16(uint32_t saddr, const void* gptr) {
    asm volatile("cp.async.cg.shared.global [%0], [%1], 16;" :: "r"(saddr), "l"(gptr));
}
#define CP_COMMIT() asm volatile("cp.async.commit_group;" ::: "memory")
#define CP_WAIT0()  asm volatile("cp.async.wait_group 0;" ::: "memory")
#define CP_WAIT1()  asm volatile("cp.async.wait_group 1;" ::: "memory")

__device__ __forceinline__ float tf32r(float x) {
    uint32_t u = __float_as_uint(x), o;
    asm("cvt.rna.tf32.f32 %0, %1;" : "=r"(o) : "r"(u));
    return __uint_as_float(o);
}

__device__ __forceinline__ void mma_tf32(float* c, const uint32_t* a, const uint32_t* b) {
    asm volatile(
        "mma.sync.aligned.m16n8k8.row.col.f32.tf32.tf32.f32 "
        "{%0,%1,%2,%3}, {%4,%5,%6,%7}, {%8,%9}, {%0,%1,%2,%3};"
        : "+f"(c[0]), "+f"(c[1]), "+f"(c[2]), "+f"(c[3])
        : "r"(a[0]), "r"(a[1]), "r"(a[2]), "r"(a[3]), "r"(b[0]), "r"(b[1]));
}

// f32x2 packed math (base sm_100-family, no arch suffix)
typedef unsigned long long u64t;
__device__ __forceinline__ u64t pk2(float x, float y) { u64t r; asm("mov.b64 %0, {%1, %2};" : "=l"(r) : "f"(x), "f"(y)); return r; }
__device__ __forceinline__ void upk2(u64t u, float& x, float& y) { asm("mov.b64 {%0, %1}, %2;" : "=f"(x), "=f"(y) : "l"(u)); }
__device__ __forceinline__ u64t fma2(u64t a, u64t b, u64t c) { u64t d; asm("fma.rn.f32x2 %0, %1, %2, %3;" : "=l"(d) : "l"(a), "l"(b), "l"(c)); return d; }
__device__ __forceinline__ u64t mul2(u64t a, u64t b) { u64t d; asm("mul.rn.f32x2 %0, %1, %2;" : "=l"(d) : "l"(a), "l"(b)); return d; }
__device__ __forceinline__ u64t add2(u64t a, u64t b) { u64t d; asm("add.rn.f32x2 %0, %1, %2;" : "=l"(d) : "l"(a), "l"(b)); return d; }

// ======================= scratch =======================
__device__ float g_x[BT*EE];
__device__ float g_h[BT*EE];
__device__ float g_qkv[BT*E3];
__device__ float g_att[BT*EE];
__device__ float g_ff[BT*FFD];
__device__ float g_nll[BT];
__device__ float g_wtqkv[LL*E3*EE];     // [l][n=1152][k=384]
__device__ float g_wto[LL*EE*EE];       // [l][n=384][k=384]
__device__ float g_wt1[LL*FFD*EE];      // [l][n=1536][k=384]
__device__ float g_wt2[LL*EE*FFD];      // [l][n=384][k=1536]
__device__ float g_woutT[VV*EE];        // [v][e]

// ======================= embedding =======================
__global__ void embed_kernel(const int* __restrict__ idx,
                             const float* __restrict__ tok,
                             const float* __restrict__ pos) {
    int i = blockIdx.x * blockDim.x + threadIdx.x;
    if (i >= BT * EE) return;
    int e  = i % EE;
    int bt = i / EE;
    int t  = bt % TT;
    g_x[i] = tok[idx[bt] * EE + e] + pos[t * EE + e];
}

// ======================= layernorm (R=1: tf32-round output) =======================
template <int R>
__global__ void ln_kernel(const float* __restrict__ s, const float* __restrict__ b) {
    int tok = blockIdx.x;
    int tid = threadIdx.x;                 // 128 threads
    const float* row = g_x + (size_t)tok * EE;
    float v0 = row[tid], v1 = row[tid + 128], v2 = row[tid + 256];

    float sum = v0 + v1 + v2;
    __shared__ float red[4], red2[4];
    #pragma unroll
    for (int o = 16; o; o >>= 1) sum += __shfl_xor_sync(~0u, sum, o);
    if ((tid & 31) == 0) red[tid >> 5] = sum;
    __syncthreads();
    float mean = (red[0] + red[1] + red[2] + red[3]) * (1.f / EE);

    float d0 = v0 - mean, d1 = v1 - mean, d2 = v2 - mean;
    float vs = d0 * d0 + d1 * d1 + d2 * d2;
    #pragma unroll
    for (int o = 16; o; o >>= 1) vs += __shfl_xor_sync(~0u, vs, o);
    if ((tid & 31) == 0) red2[tid >> 5] = vs;
    __syncthreads();
    float var = (red2[0] + red2[1] + red2[2] + red2[3]) * (1.f / EE);
    float inv = rsqrtf(var + EPSV);

    float* out = g_h + (size_t)tok * EE;
    float o0 = d0 * inv * s[tid]       + b[tid];
    float o1 = d1 * inv * s[tid + 128] + b[tid + 128];
    float o2 = d2 * inv * s[tid + 256] + b[tid + 256];
    if (R) { o0 = tf32r(o0); o1 = tf32r(o1); o2 = tf32r(o2); }
    out[tid] = o0; out[tid + 128] = o1; out[tid + 256] = o2;
}

// ======================= weight transposes =======================
__global__ void tq_all(const float* __restrict__ Wq, const float* __restrict__ Wk,
                       const float* __restrict__ Wv) {
    int i = blockIdx.x * blockDim.x + threadIdx.x;
    if (i >= LL * HH * EE * DHH) return;
    int d = i % DHH;
    int e = (i / DHH) % EE;
    int h = (i / (DHH * EE)) % HH;
    int l = i / (DHH * EE * HH);
    int n = h * DHH + d;
    float* dst = g_wtqkv + (size_t)l * E3 * EE;
    dst[(size_t)n * EE + e]            = tf32r(Wq[i]);
    dst[(size_t)(EE + n) * EE + e]     = tf32r(Wk[i]);
    dst[(size_t)(2 * EE + n) * EE + e] = tf32r(Wv[i]);
}

// out[l][n][k] = tf32round(in[l][k][n])
__global__ void t_generic(const float* __restrict__ in, float* __restrict__ out,
                          int Kd, int Nd, int total) {
    int i = blockIdx.x * blockDim.x + threadIdx.x;
    if (i >= total) return;
    int k = i % Kd;
    int n = (i / Kd) % Nd;
    int l = i / (Kd * Nd);
    out[i] = tf32r(in[(size_t)l * Kd * Nd + (size_t)k * Nd + n]);
}

__global__ void twout_kernel(const float* __restrict__ Wout) {
    int i = blockIdx.x * blockDim.x + threadIdx.x;
    if (i >= VV * EE) return;
    int e = i % EE;
    int v = i / EE;
    g_woutT[i] = Wout[(size_t)e * VV + v];
}

// ======================= tf32 mma.sync GEMM: C[M,N] = A[M,K] * Bw[N,K]^T =======================
// CTA 128x128, BK=32, 256 threads = 8 warps (4 M x 2 N), warp tile 32x64.
// smem: As/Bs [128][36] padded, double buffered via cp.async.
// MODE bits: 1=+bias[n], 2=+resid, 4=relu, 8=tf32-round output
#define SROW 36
#define SBUF (128*SROW)          // floats per tile buffer

template <int MODE>
__global__ void __launch_bounds__(256) gemm_mma(
    const float* __restrict__ A, const float* __restrict__ Bw,
    const float* __restrict__ bias, const float* __restrict__ resid,
    float* __restrict__ C, int N, int K)
{
    extern __shared__ float smem[];           // [4 * SBUF] floats = 73728 B
    uint32_t sbase = smem_to_u32(smem);
    int tid  = threadIdx.x;
    int lane = tid & 31, warp = tid >> 5;
    int wy = warp & 3, wx = warp >> 2;        // 4 M-warps x 2 N-warps
    int g = lane >> 2, t4 = lane & 3;
    int n0 = blockIdx.x * 128;
    int m0 = blockIdx.y * 128;

    float acc[2][8][4];
    #pragma unroll
    for (int mf = 0; mf < 2; mf++)
        #pragma unroll
        for (int nf = 0; nf < 8; nf++)
            #pragma unroll
            for (int q = 0; q < 4; q++) acc[mf][nf][q] = 0.f;

    const int nk = K >> 5;
    int lr = tid >> 3;                         // load row base pattern
    int lc = (tid & 7) << 2;                   // load col (float offset)

    // tile loader: A rows m0+r cols kc*32+lc ; B rows n0+r
    auto load_tile = [&](int kc, int buf) {
        const float* Ag = A  + (size_t)m0 * K + (size_t)kc * 32;
        const float* Bg = Bw + (size_t)n0 * K + (size_t)kc * 32;
        uint32_t sA = sbase + (uint32_t)(buf * SBUF) * 4u;
        uint32_t sB = sbase + (uint32_t)((2 + buf) * SBUF) * 4u;
        #pragma unroll
        for (int it = 0; it < 4; it++) {
            int i = tid + it * 256;
            int r = i >> 3, c = (i & 7) << 2;
            cp_async16(sA + (uint32_t)(r * SROW + c) * 4u, Ag + (size_t)r * K + c);
        }
        #pragma unroll
        for (int it = 0; it < 4; it++) {
            int i = tid + it * 256;
            int r = i >> 3, c = (i & 7) << 2;
            cp_async16(sB + (uint32_t)(r * SROW + c) * 4u, Bg + (size_t)r * K + c);
        }
    };
    (void)lr; (void)lc;

    load_tile(0, 0);
    CP_COMMIT();

    for (int kc = 0; kc < nk; kc++) {
        int buf = kc & 1;
        if (kc + 1 < nk) { load_tile(kc + 1, buf ^ 1); CP_COMMIT(); CP_WAIT1(); }
        else            { CP_WAIT0(); }
        __syncthreads();

        const float* sA = smem + buf * SBUF;
        const float* sB = smem + (2 + buf) * SBUF;
        #pragma unroll
        for (int ks = 0; ks < 4; ks++) {
            int k0 = ks * 8;
            uint32_t afr[2][4];
            #pragma unroll
            for (int mf = 0; mf < 2; mf++) {
                int mb = wy * 32 + mf * 16;
                afr[mf][0] = __float_as_uint(sA[(mb + g)     * SROW + k0 + t4]);
                afr[mf][1] = __float_as_uint(sA[(mb + g + 8) * SROW + k0 + t4]);
                afr[mf][2] = __float_as_uint(sA[(mb + g)     * SROW + k0 + t4 + 4]);
                afr[mf][3] = __float_as_uint(sA[(mb + g + 8) * SROW + k0 + t4 + 4]);
            }
            uint32_t bfr[8][2];
            #pragma unroll
            for (int nf = 0; nf < 8; nf++) {
                int nb = wx * 64 + nf * 8;
                bfr[nf][0] = __float_as_uint(sB[(nb + g) * SROW + k0 + t4]);
                bfr[nf][1] = __float_as_uint(sB[(nb + g) * SROW + k0 + t4 + 4]);
            }
            #pragma unroll
            for (int mf = 0; mf < 2; mf++)
                #pragma unroll
                for (int nf = 0; nf < 8; nf++)
                    mma_tf32(acc[mf][nf], afr[mf], bfr[nf]);
        }
        __syncthreads();
    }

    // epilogue
    #pragma unroll
    for (int mf = 0; mf < 2; mf++) {
        #pragma unroll
        for (int nf = 0; nf < 8; nf++) {
            int m = m0 + wy * 32 + mf * 16 + g;
            int n = n0 + wx * 64 + nf * 8 + t4 * 2;
            #pragma unroll
            for (int rr = 0; rr < 2; rr++) {
                int mm = m + rr * 8;
                float x0 = acc[mf][nf][rr * 2];
                float x1 = acc[mf][nf][rr * 2 + 1];
                if (MODE & 1) { x0 += __ldg(bias + n); x1 += __ldg(bias + n + 1); }
                if (MODE & 2) {
                    const float* rp = resid + (size_t)mm * N + n;
                    x0 += rp[0]; x1 += rp[1];
                }
                if (MODE & 4) { x0 = fmaxf(x0, 0.f); x1 = fmaxf(x1, 0.f); }
                if (MODE & 8) { x0 = tf32r(x0); x1 = tf32r(x1); }
                float2 o = make_float2(x0, x1);
                *(float2*)(C + (size_t)mm * N + n) = o;
            }
        }
    }
}

// ======================= attention: f32x2 packed flash =======================
__global__ void attn_kernel() {
    extern __shared__ float sm[];
    float* Ks = sm;                 // [256][64]
    float* Vs = sm + TT * DHH;      // [256][64]
    int b = blockIdx.x / HH;
    int h = blockIdx.x % HH;
    int tid = threadIdx.x;          // 256

    const float* base = g_qkv + (size_t)b * TT * E3;
    for (int i = tid; i < TT * DHH / 4; i += blockDim.x) {
        int srow = i >> 4;
        int c4 = (i & 15) << 2;
        *(float4*)&Ks[srow * DHH + c4] = *(const float4*)(base + (size_t)srow * E3 + EE + h * DHH + c4);
        *(float4*)&Vs[srow * DHH + c4] = *(const float4*)(base + (size_t)srow * E3 + 2 * EE + h * DHH + c4);
    }
    __syncthreads();

    int t = tid;
    u64t q2[32], acc2[32];
    const float* qp = base + (size_t)t * E3 + h * DHH;
    #pragma unroll
    for (int i = 0; i < 32; i++) {
        q2[i] = pk2(qp[2 * i] * 0.125f, qp[2 * i + 1] * 0.125f);
        acc2[i] = 0ull;
    }
    float m = -1e30f, l = 0.f;

    for (int s = 0; s <= t; s++) {
        const ulonglong2* k2 = (const ulonglong2*)&Ks[s * DHH];
        u64t da = 0ull, db = 0ull, dc = 0ull, dd = 0ull;
        #pragma unroll
        for (int i = 0; i < 8; i++) {
            ulonglong2 k01 = k2[2 * i];
            ulonglong2 k23 = k2[2 * i + 1];
            da = fma2(q2[4 * i],     k01.x, da);
            db = fma2(q2[4 * i + 1], k01.y, db);
            dc = fma2(q2[4 * i + 2], k23.x, dc);
            dd = fma2(q2[4 * i + 3], k23.y, dd);
        }
        u64t dt = add2(add2(da, db), add2(dc, dd));
        float sx, sy; upk2(dt, sx, sy);
        float sc = sx + sy;

        float nm = fmaxf(m, sc);
        float corr = __expf(m - nm);
        float p = __expf(sc - nm);
        l = l * corr + p;
        u64t c2 = pk2(corr, corr), p2 = pk2(p, p);
        const ulonglong2* v2 = (const ulonglong2*)&Vs[s * DHH];
        #pragma unroll
        for (int i = 0; i < 16; i++) {
            ulonglong2 vv = v2[i];
            acc2[2 * i]     = fma2(acc2[2 * i],     c2, mul2(p2, vv.x));
            acc2[2 * i + 1] = fma2(acc2[2 * i + 1], c2, mul2(p2, vv.y));
        }
        m = nm;
    }

    float inv = 1.f / l;
    float* op = g_att + ((size_t)(b * TT + t)) * EE + h * DHH;
    #pragma unroll
    for (int i = 0; i < 32; i++) {
        float x, y; upk2(acc2[i], x, y);
        op[2 * i]     = tf32r(x * inv);
        op[2 * i + 1] = tf32r(y * inv);
    }
}

// ======================= fused logits + log_softmax + nll =======================
__global__ void logits_kernel(const float* __restrict__ bout,
                              const int* __restrict__ tgt, float* __restrict__ out) {
    __shared__ float hs[EE];
    __shared__ float sl[128];
    __shared__ float slog[VV];
    int tok = blockIdx.x;
    int tid = threadIdx.x;          // 128
    const float* row = g_h + (size_t)tok * EE;
    hs[tid] = row[tid]; hs[tid + 128] = row[tid + 128]; hs[tid + 256] = row[tid + 256];
    __syncthreads();

    float logit = -1e30f;
    if (tid < VV) {
        float s = bout[tid];
        const float4* w4 = (const float4*)(g_woutT + (size_t)tid * EE);
        #pragma unroll 8
        for (int e = 0; e < EE / 4; e++) {
            float4 w = w4[e];
            s = fmaf(hs[4 * e], w.x, s);
            s = fmaf(hs[4 * e + 1], w.y, s);
            s = fmaf(hs[4 * e + 2], w.z, s);
            s = fmaf(hs[4 * e + 3], w.w, s);
        }
        logit = s;
        slog[tid] = s;
        out[(size_t)tok * VV + tid] = s;
    }
    sl[tid] = logit;
    __syncthreads();
    for (int o = 64; o; o >>= 1) { if (tid < o) sl[tid] = fmaxf(sl[tid], sl[tid + o]); __syncthreads(); }
    float mx = sl[0];
    __syncthreads();
    sl[tid] = (tid < VV) ? __expf(logit - mx) : 0.f;
    __syncthreads();
    for (int o = 64; o; o >>= 1) { if (tid < o) sl[tid] += sl[tid + o]; __syncthreads(); }
    if (tid == 0) {
        float logZ = mx + __logf(sl[0]);
        g_nll[tok] = logZ - slog[tgt[tok]];
    }
}

// ======================= deterministic loss reduction =======================
__global__ void loss_kernel(float* __restrict__ out) {
    __shared__ float red[256];
    float s = 0.f;
    for (int i = threadIdx.x; i < BT; i += 256) s += g_nll[i];
    red[threadIdx.x] = s;
    __syncthreads();
    for (int o = 128; o; o >>= 1) { if (threadIdx.x < o) red[threadIdx.x] += red[threadIdx.x + o]; __syncthreads(); }
    if (threadIdx.x == 0) out[(size_t)BT * VV] = red[0] * (1.f / BT);
}

// ======================= host orchestration =======================
extern "C" void kernel_launch(void* const* d_in, const int* in_sizes, int n_in,
                              void* d_out, int out_size) {
    const int*   idx  = (const int*)d_in[0];
    const int*   tgt  = (const int*)d_in[1];
    const float* tok  = (const float*)d_in[2];
    const float* pos  = (const float*)d_in[3];
    const float* Wq   = (const float*)d_in[4];
    const float* Wk   = (const float*)d_in[5];
    const float* Wv   = (const float*)d_in[6];
    const float* Wo   = (const float*)d_in[7];
    const float* bo   = (const float*)d_in[8];
    const float* l1s  = (const float*)d_in[9];
    const float* l1b  = (const float*)d_in[10];
    const float* l2s  = (const float*)d_in[11];
    const float* l2b  = (const float*)d_in[12];
    const float* W1   = (const float*)d_in[13];
    const float* b1   = (const float*)d_in[14];
    const float* W2   = (const float*)d_in[15];
    const float* b2   = (const float*)d_in[16];
    const float* lnfs = (const float*)d_in[17];
    const float* lnfb = (const float*)d_in[18];
    const float* Wout = (const float*)d_in[19];
    const float* bout = (const float*)d_in[20];
    float* out = (float*)d_out;

    const int GSMEM = 4 * SBUF * (int)sizeof(float);   // 73728
    cudaFuncSetAttribute(gemm_mma<0>,  cudaFuncAttributeMaxDynamicSharedMemorySize, GSMEM);
    cudaFuncSetAttribute(gemm_mma<3>,  cudaFuncAttributeMaxDynamicSharedMemorySize, GSMEM);
    cudaFuncSetAttribute(gemm_mma<13>, cudaFuncAttributeMaxDynamicSharedMemorySize, GSMEM);
    cudaFuncSetAttribute(attn_kernel, cudaFuncAttributeMaxDynamicSharedMemorySize,
                         2 * TT * DHH * (int)sizeof(float));

    float *px, *ph, *pqkv, *patt, *pff, *pwtqkv, *pwto, *pwt1, *pwt2;
    cudaGetSymbolAddress((void**)&px,     g_x);
    cudaGetSymbolAddress((void**)&ph,     g_h);
    cudaGetSymbolAddress((void**)&pqkv,   g_qkv);
    cudaGetSymbolAddress((void**)&patt,   g_att);
    cudaGetSymbolAddress((void**)&pff,    g_ff);
    cudaGetSymbolAddress((void**)&pwtqkv, g_wtqkv);
    cudaGetSymbolAddress((void**)&pwto,   g_wto);
    cudaGetSymbolAddress((void**)&pwt1,   g_wt1);
    cudaGetSymbolAddress((void**)&pwt2,   g_wt2);

    embed_kernel<<<(BT * EE + 255) / 256, 256>>>(idx, tok, pos);
    tq_all<<<(LL * HH * EE * DHH + 255) / 256, 256>>>(Wq, Wk, Wv);
    t_generic<<<(LL * EE * EE + 255) / 256, 256>>>(Wo, pwto, EE, EE, LL * EE * EE);
    t_generic<<<(LL * EE * FFD + 255) / 256, 256>>>(W1, pwt1, EE, FFD, LL * EE * FFD);
    t_generic<<<(LL * FFD * EE + 255) / 256, 256>>>(W2, pwt2, FFD, EE, LL * FFD * EE);
    twout_kernel<<<(VV * EE + 255) / 256, 256>>>(Wout);

    for (int l = 0; l < LL; l++) {
        ln_kernel<1><<<BT, 128>>>(l1s + l * EE, l1b + l * EE);
        // qkv = h @ WqkvT   [32768,384] x [1152,384]^T
        gemm_mma<0><<<dim3(E3 / 128, BT / 128), 256, GSMEM>>>(
            ph, pwtqkv + (size_t)l * E3 * EE, nullptr, nullptr, pqkv, E3, EE);
        attn_kernel<<<BB * HH, TT, 2 * TT * DHH * sizeof(float)>>>();
        // x = x + att @ Wo + bo
        gemm_mma<3><<<dim3(EE / 128, BT / 128), 256, GSMEM>>>(
            patt, pwto + (size_t)l * EE * EE, bo + l * EE, px, px, EE, EE);
        ln_kernel<1><<<BT, 128>>>(l2s + l * EE, l2b + l * EE);
        // ff = tf32round(relu(h @ W1 + b1))
        gemm_mma<13><<<dim3(FFD / 128, BT / 128), 256, GSMEM>>>(
            ph, pwt1 + (size_t)l * FFD * EE, b1 + l * FFD, nullptr, pff, FFD, EE);
        // x = x + ff @ W2 + b2
        gemm_mma<3><<<dim3(EE / 128, BT / 128), 256, GSMEM>>>(
            pff, pwt2 + (size_t)l * EE * FFD, b2 + l * EE, px, px, EE, FFD);
    }

    ln_kernel<0><<<BT, 128>>>(lnfs, lnfb);
    logits_kernel<<<BT, 128>>>(bout, tgt, out);
    loss_kernel<<<1, 256>>>(out);
}